// round 5
// baseline (speedup 1.0000x reference)
#include <cuda_runtime.h>
#include <cuda_bf16.h>
#include <cooperative_groups.h>
#include <cstdint>

namespace cg = cooperative_groups;

#define S_LEN 2048
#define B_N   64
#define W5    50
#define E_N   128
#define H_N   256
#define G_N   1024

typedef unsigned long long ull;

// ---------------- static device scratch (allocation-free) ----------------
__device__ float g_emb[(size_t)S_LEN * B_N * E_N];      // [s][b][e]
__device__ float g_xg [(size_t)S_LEN * B_N * G_N];      // [s][b][g]
__device__ float g_hs [(size_t)S_LEN * 16 * H_N * 4];   // [s][cl][j][b4]

__device__ __forceinline__ float sigf(float x) { return 1.0f / (1.0f + __expf(-x)); }
__device__ __forceinline__ float tanhf_fast(float x) {
    float e = __expf(2.0f * x);
    return 1.0f - 2.0f / (e + 1.0f);
}

__device__ __forceinline__ ull pack2(float lo, float hi) {
    ull r; asm("mov.b64 %0, {%1, %2};" : "=l"(r) : "f"(lo), "f"(hi)); return r;
}
__device__ __forceinline__ void unpack2(ull v, float& lo, float& hi) {
    asm("mov.b64 {%0, %1}, %2;" : "=f"(lo), "=f"(hi) : "l"(v));
}
__device__ __forceinline__ void fma2(ull& d, ull a, ull b) {
    asm("fma.rn.f32x2 %0, %1, %2, %0;" : "+l"(d) : "l"(a), "l"(b));
}
__device__ __forceinline__ ull add2(ull a, ull b) {
    ull r; asm("add.rn.f32x2 %0, %1, %2;" : "=l"(r) : "l"(a), "l"(b)); return r;
}

__device__ __forceinline__ uint32_t smem_u32(const void* p) {
    uint32_t a;
    asm("{ .reg .u64 t; cvta.to.shared.u64 t, %1; cvt.u32.u64 %0, t; }" : "=r"(a) : "l"(p));
    return a;
}

#define MBAR_INIT(addr, cnt) \
    asm volatile("mbarrier.init.shared.b64 [%0], %1;" :: "r"(addr), "r"(cnt) : "memory")

// arrive with cluster-scope release on (possibly remote) CTA `rank`'s barrier
#define MBAR_ARRIVE_CLUSTER(local_addr, rank)                                   \
    asm volatile(                                                               \
        "{\n\t.reg .b32 ra;\n\t"                                                \
        "mapa.shared::cluster.u32 ra, %0, %1;\n\t"                              \
        "mbarrier.arrive.release.cluster.shared::cluster.b64 _, [ra];\n\t}"     \
        :: "r"(local_addr), "r"(rank) : "memory")

// wait with cluster-scope acquire
#define MBAR_WAIT_CLUSTER(addr, parity) do {                                    \
    uint32_t _done;                                                             \
    asm volatile(                                                               \
        "{\n\t.reg .pred p;\n\t"                                                \
        "mbarrier.try_wait.parity.acquire.cluster.shared::cta.b64 p, [%1], %2;\n\t" \
        "selp.b32 %0, 1, 0, p;\n\t}"                                            \
        : "=r"(_done) : "r"(addr), "r"(parity) : "memory");                     \
    if (!_done) {                                                               \
        asm volatile(                                                           \
            "{\n\t.reg .pred P1;\n\t"                                           \
            "WL_%=:\n\t"                                                        \
            "mbarrier.try_wait.parity.acquire.cluster.shared::cta.b64 P1, [%0], %1, 0x989680;\n\t" \
            "@P1 bra.uni WD_%=;\n\t"                                            \
            "bra.uni WL_%=;\n\t"                                                \
            "WD_%=:\n\t}"                                                       \
            :: "r"(addr), "r"(parity) : "memory");                              \
    }                                                                           \
} while (0)

// =============== Phase 1a: emb = relu(pw @ Wemb^T + bemb) ===============
__global__ void __launch_bounds__(256) emb_kernel(const float* __restrict__ pw,
                                                  const float* __restrict__ Wemb,
                                                  const float* __restrict__ bemb) {
    __shared__ float pw_s[64 * 51];
    __shared__ float we_s[128 * 51];
    const int s = blockIdx.x;
    const int t = threadIdx.x;

    for (int i = t; i < 64 * 50; i += 256) {
        int b = i / 50, k = i - b * 50;
        pw_s[b * 51 + k] = pw[((size_t)b * S_LEN + s) * W5 + k];
    }
    for (int i = t; i < 128 * 50; i += 256) {
        int e = i / 50, k = i - e * 50;
        we_s[e * 51 + k] = Wemb[e * 50 + k];
    }
    __syncthreads();

    const int e = t & 127, bh = t >> 7;
    float wreg[50];
#pragma unroll
    for (int k = 0; k < 50; k++) wreg[k] = we_s[e * 51 + k];
    const float be = bemb[e];
    float* outp = g_emb + (size_t)s * (B_N * E_N);
    for (int bb = 0; bb < 32; bb++) {
        int b = bh * 32 + bb;
        float acc = be;
#pragma unroll
        for (int k = 0; k < 50; k++) acc = fmaf(pw_s[b * 51 + k], wreg[k], acc);
        outp[b * 128 + e] = fmaxf(acc, 0.0f);
    }
}

// =============== Phase 1b: x_gates[s][b][g] = Wih @ emb^T + (bih+bhh) ===============
#define XP 68
#define TPCH 69
__global__ void __launch_bounds__(128) xgates_kernel(const float* __restrict__ Wih,
                                                     const float* __restrict__ bih,
                                                     const float* __restrict__ bhh) {
    extern __shared__ float sm[];
    float* wT = sm;                 // [e=128][g=64] pitch XP
    float* eT = sm + 128 * XP;      // [e=128][b=64] pitch XP
    float* tr = eT + 128 * XP;      // [b=64][g=64]  pitch TPCH
    const int s = blockIdx.y, gt = blockIdx.x;
    const int t = threadIdx.x;

    for (int i = t; i < 64 * 128; i += 128) {
        int e = i & 127, g = i >> 7;
        wT[e * XP + g] = Wih[((size_t)(gt * 64 + g)) * 128 + e];
    }
    const float* embp = g_emb + (size_t)s * (B_N * E_N);
    for (int i = t; i < 64 * 128; i += 128) {
        int e = i & 127, b = i >> 7;
        eT[e * XP + b] = embp[b * 128 + e];
    }
    __syncthreads();

    const int gq = t >> 4;
    const int bq = t & 15;
    float acc[8][4];
#pragma unroll
    for (int i = 0; i < 8; i++)
#pragma unroll
        for (int j = 0; j < 4; j++) acc[i][j] = 0.0f;

#pragma unroll 4
    for (int e = 0; e < 128; e++) {
        float4 w0 = *(float4*)&wT[e * XP + gq * 8];
        float4 w1 = *(float4*)&wT[e * XP + gq * 8 + 4];
        float4 hv = *(float4*)&eT[e * XP + bq * 4];
        float w[8] = {w0.x, w0.y, w0.z, w0.w, w1.x, w1.y, w1.z, w1.w};
        float x[4] = {hv.x, hv.y, hv.z, hv.w};
#pragma unroll
        for (int i = 0; i < 8; i++)
#pragma unroll
            for (int j = 0; j < 4; j++) acc[i][j] = fmaf(w[i], x[j], acc[i][j]);
    }

#pragma unroll
    for (int i = 0; i < 8; i++) {
        int gl = gq * 8 + i;
        int gg = gt * 64 + gl;
        float bs = bih[gg] + bhh[gg];
#pragma unroll
        for (int j = 0; j < 4; j++) tr[(bq * 4 + j) * TPCH + gl] = acc[i][j] + bs;
    }
    __syncthreads();

    float* xgp = g_xg + (size_t)s * (B_N * G_N);
    for (int idx = t; idx < 64 * 64; idx += 128) {
        int b = idx >> 6, g = idx & 63;
        xgp[(size_t)b * G_N + gt * 64 + g] = tr[b * TPCH + g];
    }
}

// =============== Phase 2: clustered LSTM scan, mbarrier systolic exchange ===============
// 16 clusters x 8 CTAs x 256 threads. Cluster cl owns batches 4cl..4cl+3.
// CTA rank owns hidden cols j = 32*rank..+31. Thread: rg=t>>3 (j-local), kq=t&7 (k-split).
__global__ void __launch_bounds__(256, 1) __cluster_dims__(8, 1, 1)
lstm_kernel(const float* __restrict__ Whh,
            const float* __restrict__ h0,
            const float* __restrict__ c0) {
    __shared__ float4 h_s[2][256];        // [buf][k] x 4 batches
    __shared__ float  xg_s[2][512];       // [buf][(b4*4+gate)*32 + jl]
    __shared__ ull    mbar[2];

    cg::cluster_group cluster = cg::this_cluster();
    const int rank = (int)cluster.block_rank();
    const int cl   = (int)(blockIdx.x >> 3);
    const int t    = threadIdx.x;
    const int kq   = t & 7;
    const int rg   = t >> 3;
    const int jg   = rank * 32 + rg;

    const uint32_t bar0 = smem_u32(&mbar[0]);
    const uint32_t bar1 = smem_u32(&mbar[1]);
    if (t == 0) { MBAR_INIT(bar0, 8); MBAR_INIT(bar1, 8); }

    // register-resident W_hh pairs: (Wi,Wf), (Wg,Wo) for column jg, k = 8*kk+kq
    ull wif[32], wgo[32];
#pragma unroll
    for (int kk = 0; kk < 32; kk++) {
        int k = (kk << 3) | kq;
        wif[kk] = pack2(Whh[(size_t)(0 * 256 + jg) * 256 + k],
                        Whh[(size_t)(1 * 256 + jg) * 256 + k]);
        wgo[kk] = pack2(Whh[(size_t)(2 * 256 + jg) * 256 + k],
                        Whh[(size_t)(3 * 256 + jg) * 256 + k]);
    }

    float4* peer[8];
#pragma unroll
    for (int p = 0; p < 8; p++) peer[p] = cluster.map_shared_rank(&h_s[0][0], p);

    // initial h into buf 0 (h0 is [b][j]); every CTA builds its own full copy
    h_s[0][t] = make_float4(h0[(4 * cl + 0) * 256 + t],
                            h0[(4 * cl + 1) * 256 + t],
                            h0[(4 * cl + 2) * 256 + t],
                            h0[(4 * cl + 3) * 256 + t]);

    float c = 0.0f;
    if (kq < 4) c = c0[(4 * cl + kq) * 256 + jg];

    // stage xg for s=0 (coalesced 128B chunks)
    for (int idx = t; idx < 512; idx += 256) {
        int ch = idx >> 5, l = idx & 31;
        int b4 = ch >> 2, gate = ch & 3;
        xg_s[0][idx] = g_xg[((size_t)0 * B_N + 4 * cl + b4) * G_N + gate * 256 + rank * 32 + l];
    }
    __syncthreads();
    asm volatile("barrier.cluster.arrive.aligned;" ::: "memory");
    asm volatile("barrier.cluster.wait.aligned;" ::: "memory");

    int ph0 = 0, ph1 = 0;
    const int lane = t & 31;
    const int obase = lane & 24;

    for (int s = 0; s < S_LEN; s++) {
        const int buf = s & 1;

        // issue coalesced LDGs for next step's xg (consumed next step; huge cover)
        float nx0 = 0.f, nx1 = 0.f;
        if (s + 1 < S_LEN) {
            const float* xp = g_xg + (size_t)(s + 1) * (B_N * G_N);
            {
                int ch = t >> 5, l = t & 31;
                nx0 = __ldg(&xp[(size_t)(4 * cl + (ch >> 2)) * G_N + (ch & 3) * 256 + rank * 32 + l]);
            }
            {
                int i2 = t + 256, ch = i2 >> 5, l = i2 & 31;
                nx1 = __ldg(&xp[(size_t)(4 * cl + (ch >> 2)) * G_N + (ch & 3) * 256 + rank * 32 + l]);
            }
        }

        // wait for h(s) buffer (all 8 producers arrived); acquire makes stores visible
        if (s > 0) {
            if (buf) { MBAR_WAIT_CLUSTER(bar1, ph1); ph1 ^= 1; }
            else     { MBAR_WAIT_CLUSTER(bar0, ph0); ph0 ^= 1; }
        }

        // matvec over h_s[buf]
        const float4* hb = h_s[buf];
        ull aif0 = 0, aif1 = 0, aif2 = 0, aif3 = 0;
        ull ago0 = 0, ago1 = 0, ago2 = 0, ago3 = 0;
#pragma unroll
        for (int kk = 0; kk < 32; kk++) {
            float4 hv = hb[(kk << 3) | kq];
            ull b0 = pack2(hv.x, hv.x), b1 = pack2(hv.y, hv.y);
            ull b2 = pack2(hv.z, hv.z), b3 = pack2(hv.w, hv.w);
            fma2(aif0, wif[kk], b0); fma2(ago0, wgo[kk], b0);
            fma2(aif1, wif[kk], b1); fma2(ago1, wgo[kk], b1);
            fma2(aif2, wif[kk], b2); fma2(ago2, wgo[kk], b2);
            fma2(aif3, wif[kk], b3); fma2(ago3, wgo[kk], b3);
        }

        // butterfly allreduce over 8 kq lanes
#pragma unroll
        for (int off = 1; off < 8; off <<= 1) {
            aif0 = add2(aif0, __shfl_xor_sync(0xffffffffu, aif0, off));
            aif1 = add2(aif1, __shfl_xor_sync(0xffffffffu, aif1, off));
            aif2 = add2(aif2, __shfl_xor_sync(0xffffffffu, aif2, off));
            aif3 = add2(aif3, __shfl_xor_sync(0xffffffffu, aif3, off));
            ago0 = add2(ago0, __shfl_xor_sync(0xffffffffu, ago0, off));
            ago1 = add2(ago1, __shfl_xor_sync(0xffffffffu, ago1, off));
            ago2 = add2(ago2, __shfl_xor_sync(0xffffffffu, ago2, off));
            ago3 = add2(ago3, __shfl_xor_sync(0xffffffffu, ago3, off));
        }

        // park staged xg for next step in the other smem buffer
        if (s + 1 < S_LEN) {
            xg_s[buf ^ 1][t]       = nx0;
            xg_s[buf ^ 1][t + 256] = nx1;
        }

        // lanes kq=0..3 update batch b=kq for column jg
        float hval = 0.0f;
        if (kq < 4) {
            ull aif = (kq == 0) ? aif0 : (kq == 1) ? aif1 : (kq == 2) ? aif2 : aif3;
            ull ago = (kq == 0) ? ago0 : (kq == 1) ? ago1 : (kq == 2) ? ago2 : ago3;
            float si, sf, sg, so;
            unpack2(aif, si, sf);
            unpack2(ago, sg, so);
            const float* xs = &xg_s[buf][kq * 128 + rg];
            float iv = sigf(si + xs[0]);
            float fv = sigf(sf + xs[32]);
            float gv = tanhf_fast(sg + xs[64]);
            float ov = sigf(so + xs[96]);
            c = fv * c + iv * gv;
            hval = ov * tanhf_fast(c);
        }

        // gather 4 batch values; broadcast h to all 8 CTAs' next buffer
        float hx = __shfl_sync(0xffffffffu, hval, obase + 0);
        float hy = __shfl_sync(0xffffffffu, hval, obase + 1);
        float hz = __shfl_sync(0xffffffffu, hval, obase + 2);
        float hw = __shfl_sync(0xffffffffu, hval, obase + 3);
        if (kq == 0) {
            float4 o4 = make_float4(hx, hy, hz, hw);
            *(float4*)&g_hs[(((size_t)s * 16 + cl) * 256 + jg) * 4] = o4;
            if (s + 1 < S_LEN) {
                int slot = ((buf ^ 1) << 8) + jg;
#pragma unroll
                for (int p = 0; p < 8; p++) peer[p][slot] = o4;
            }
        }

        __syncthreads();   // all of this CTA's peer-stores done
        if (s + 1 < S_LEN && t == 0) {
            const uint32_t nb = (buf ^ 1) ? bar1 : bar0;
#pragma unroll
            for (int p = 0; p < 8; p++) MBAR_ARRIVE_CLUSTER(nb, p);
        }
    }

    asm volatile("barrier.cluster.arrive.aligned;" ::: "memory");
    asm volatile("barrier.cluster.wait.aligned;" ::: "memory");
}

__global__ void dummy_kernel() {}

// =============== Phase 3: readout, g_hs is [s][cl][j][b4] ===============
__global__ void __launch_bounds__(256) readout_kernel(const float* __restrict__ Wout,
                                                      const float* __restrict__ bout,
                                                      float* __restrict__ y) {
    __shared__ float part[4][64];
    const int s = blockIdx.x;
    const int t = threadIdx.x;
    const int p = t & 63;
    const int q = t >> 6;
    const float* hp = g_hs + (((size_t)s * 16 + (p >> 2)) * 256) * 4 + (p & 3);
    float acc = 0.0f;
#pragma unroll 8
    for (int j = q * 64; j < q * 64 + 64; j++)
        acc = fmaf(hp[(size_t)j * 4], Wout[j], acc);
    part[q][p] = acc;
    __syncthreads();
    if (t < 64) {
        float v = part[0][t] + part[1][t] + part[2][t] + part[3][t] + bout[0];
        y[s * 64 + t] = sigf(v);
    }
}

// =============== host launcher ===============
extern "C" void kernel_launch(void* const* d_in, const int* in_sizes, int n_in,
                              void* d_out, int out_size) {
    const float* pw   = (const float*)d_in[0];
    const float* Wemb = (const float*)d_in[1];
    const float* bemb = (const float*)d_in[2];
    const float* Wih  = (const float*)d_in[3];
    const float* Whh  = (const float*)d_in[4];
    const float* bih  = (const float*)d_in[5];
    const float* bhh  = (const float*)d_in[6];
    const float* Wout = (const float*)d_in[7];
    const float* bout = (const float*)d_in[8];
    const float* h0   = (const float*)d_in[9];
    const float* c0   = (const float*)d_in[10];
    float* y = (float*)d_out;

    static bool attrs_set = false;
    const int xg_smem = (2 * 128 * XP + 64 * TPCH) * (int)sizeof(float);
    if (!attrs_set) {
        cudaFuncSetAttribute(xgates_kernel, cudaFuncAttributeMaxDynamicSharedMemorySize, xg_smem);
        attrs_set = true;
    }

    // launch order arranged so ncu (-s 5 -c 1) profiles xgates_kernel (launch #6)
    emb_kernel<<<S_LEN, 256>>>(pw, Wemb, bemb);
    dummy_kernel<<<1, 1>>>();
    dummy_kernel<<<1, 1>>>();
    dummy_kernel<<<1, 1>>>();
    dummy_kernel<<<1, 1>>>();
    xgates_kernel<<<dim3(16, S_LEN), 128, xg_smem>>>(Wih, bih, bhh);
    lstm_kernel<<<128, 256>>>(Whh, h0, c0);
    readout_kernel<<<S_LEN, 256>>>(Wout, bout, y);
}

// round 7
// speedup vs baseline: 1.4072x; 1.4072x over previous
#include <cuda_runtime.h>
#include <cuda_bf16.h>
#include <cooperative_groups.h>
#include <cstdint>
#include <cstdio>

namespace cg = cooperative_groups;

#define S_LEN 2048
#define B_N   64
#define W5    50
#define E_N   128
#define H_N   256
#define G_N   1024

typedef unsigned long long ull;

// ---------------- static device scratch (allocation-free) ----------------
__device__ float g_emb[(size_t)S_LEN * B_N * E_N];      // [s][b][e]
__device__ float g_xg [(size_t)S_LEN * B_N * G_N];      // [s][b][g]
__device__ float g_hs [(size_t)S_LEN * 16 * H_N * 4];   // [s][cl][j][b4]

__device__ __forceinline__ float sigf(float x) { return 1.0f / (1.0f + __expf(-x)); }
__device__ __forceinline__ float tanhf_fast(float x) {
    float e = __expf(2.0f * x);
    return 1.0f - 2.0f / (e + 1.0f);
}

__device__ __forceinline__ ull pack2(float lo, float hi) {
    ull r; asm("mov.b64 %0, {%1, %2};" : "=l"(r) : "f"(lo), "f"(hi)); return r;
}
__device__ __forceinline__ void unpack2(ull v, float& lo, float& hi) {
    asm("mov.b64 {%0, %1}, %2;" : "=f"(lo), "=f"(hi) : "l"(v));
}
__device__ __forceinline__ void fma2(ull& d, ull a, ull b) {
    asm("fma.rn.f32x2 %0, %1, %2, %0;" : "+l"(d) : "l"(a), "l"(b));
}
__device__ __forceinline__ ull add2(ull a, ull b) {
    ull r; asm("add.rn.f32x2 %0, %1, %2;" : "=l"(r) : "l"(a), "l"(b)); return r;
}
__device__ __forceinline__ ull gtimer() {
    ull t; asm volatile("mov.u64 %0, %%globaltimer;" : "=l"(t)); return t;
}

// =============== Phase 1a: emb = relu(pw @ Wemb^T + bemb) ===============
__global__ void __launch_bounds__(256) emb_kernel(const float* __restrict__ pw,
                                                  const float* __restrict__ Wemb,
                                                  const float* __restrict__ bemb) {
    __shared__ float pw_s[64 * 51];
    __shared__ float we_s[128 * 51];
    const int s = blockIdx.x;
    const int t = threadIdx.x;
    if (s == 0 && t == 0) printf("KE %llu\n", gtimer());

    for (int i = t; i < 64 * 50; i += 256) {
        int b = i / 50, k = i - b * 50;
        pw_s[b * 51 + k] = pw[((size_t)b * S_LEN + s) * W5 + k];
    }
    for (int i = t; i < 128 * 50; i += 256) {
        int e = i / 50, k = i - e * 50;
        we_s[e * 51 + k] = Wemb[e * 50 + k];
    }
    __syncthreads();

    const int e = t & 127, bh = t >> 7;
    float wreg[50];
#pragma unroll
    for (int k = 0; k < 50; k++) wreg[k] = we_s[e * 51 + k];
    const float be = bemb[e];
    float* outp = g_emb + (size_t)s * (B_N * E_N);
    for (int bb = 0; bb < 32; bb++) {
        int b = bh * 32 + bb;
        float acc = be;
#pragma unroll
        for (int k = 0; k < 50; k++) acc = fmaf(pw_s[b * 51 + k], wreg[k], acc);
        outp[b * 128 + e] = fmaxf(acc, 0.0f);
    }
}

// =============== Phase 1b: x_gates[s][b][g] = Wih @ emb^T + (bih+bhh) ===============
#define XP 68
#define TPCH 69
__global__ void __launch_bounds__(128) xgates_kernel(const float* __restrict__ Wih,
                                                     const float* __restrict__ bih,
                                                     const float* __restrict__ bhh) {
    extern __shared__ float sm[];
    float* wT = sm;                 // [e=128][g=64] pitch XP
    float* eT = sm + 128 * XP;      // [e=128][b=64] pitch XP
    float* tr = eT + 128 * XP;      // [b=64][g=64]  pitch TPCH
    const int s = blockIdx.y, gt = blockIdx.x;
    const int t = threadIdx.x;
    if (s == 0 && gt == 0 && t == 0) printf("KX %llu\n", gtimer());

    for (int i = t; i < 64 * 128; i += 128) {
        int e = i & 127, g = i >> 7;
        wT[e * XP + g] = Wih[((size_t)(gt * 64 + g)) * 128 + e];
    }
    const float* embp = g_emb + (size_t)s * (B_N * E_N);
    for (int i = t; i < 64 * 128; i += 128) {
        int e = i & 127, b = i >> 7;
        eT[e * XP + b] = embp[b * 128 + e];
    }
    __syncthreads();

    const int gq = t >> 4;
    const int bq = t & 15;
    float acc[8][4];
#pragma unroll
    for (int i = 0; i < 8; i++)
#pragma unroll
        for (int j = 0; j < 4; j++) acc[i][j] = 0.0f;

#pragma unroll 4
    for (int e = 0; e < 128; e++) {
        float4 w0 = *(float4*)&wT[e * XP + gq * 8];
        float4 w1 = *(float4*)&wT[e * XP + gq * 8 + 4];
        float4 hv = *(float4*)&eT[e * XP + bq * 4];
        float w[8] = {w0.x, w0.y, w0.z, w0.w, w1.x, w1.y, w1.z, w1.w};
        float x[4] = {hv.x, hv.y, hv.z, hv.w};
#pragma unroll
        for (int i = 0; i < 8; i++)
#pragma unroll
            for (int j = 0; j < 4; j++) acc[i][j] = fmaf(w[i], x[j], acc[i][j]);
    }

#pragma unroll
    for (int i = 0; i < 8; i++) {
        int gl = gq * 8 + i;
        int gg = gt * 64 + gl;
        float bs = bih[gg] + bhh[gg];
#pragma unroll
        for (int j = 0; j < 4; j++) tr[(bq * 4 + j) * TPCH + gl] = acc[i][j] + bs;
    }
    __syncthreads();

    float* xgp = g_xg + (size_t)s * (B_N * G_N);
    for (int idx = t; idx < 64 * 64; idx += 128) {
        int b = idx >> 6, g = idx & 63;
        xgp[(size_t)b * G_N + gt * 64 + g] = tr[b * TPCH + g];
    }
}

// =============== Phase 2: clustered LSTM scan (r4 structure + depth-2 xg prefetch) ===============
// 16 clusters x 8 CTAs x 256 threads. Cluster cl owns batches 4cl..4cl+3.
// CTA rank owns hidden cols j = 32*rank..+31. Thread: rg=t>>3 (j-local), kq=t&7 (k-split).
__global__ void __launch_bounds__(256, 1) __cluster_dims__(8, 1, 1)
lstm_kernel(const float* __restrict__ Whh,
            const float* __restrict__ h0,
            const float* __restrict__ c0) {
    __shared__ float4 h_s[2][256];          // [buf][k] x 4 batches

    cg::cluster_group cluster = cg::this_cluster();
    const int rank = (int)cluster.block_rank();
    const int cl   = (int)(blockIdx.x >> 3);
    const int t    = threadIdx.x;
    const int kq   = t & 7;
    const int rg   = t >> 3;
    const int jg   = rank * 32 + rg;
    const bool tm  = (blockIdx.x == 0 && t == 0);
    if (tm) printf("KL %llu\n", gtimer());

    // register-resident W_hh pairs
    ull wif[32], wgo[32];
#pragma unroll
    for (int kk = 0; kk < 32; kk++) {
        int k = (kk << 3) | kq;
        wif[kk] = pack2(Whh[(size_t)(0 * 256 + jg) * 256 + k],
                        Whh[(size_t)(1 * 256 + jg) * 256 + k]);
        wgo[kk] = pack2(Whh[(size_t)(2 * 256 + jg) * 256 + k],
                        Whh[(size_t)(3 * 256 + jg) * 256 + k]);
    }

    float4* peer[8];
#pragma unroll
    for (int p = 0; p < 8; p++) peer[p] = cluster.map_shared_rank(&h_s[0][0], p);

    h_s[0][t] = make_float4(h0[(4 * cl + 0) * 256 + t],
                            h0[(4 * cl + 1) * 256 + t],
                            h0[(4 * cl + 2) * 256 + t],
                            h0[(4 * cl + 3) * 256 + t]);
    float c = 0.0f;
    if (kq < 4) c = c0[(4 * cl + kq) * 256 + jg];

    // depth-2 xg prefetch registers: cur (step s), nxt (step s+1)
    float xc0 = 0.f, xc1 = 0.f, xc2 = 0.f, xc3 = 0.f;
    float xn0 = 0.f, xn1 = 0.f, xn2 = 0.f, xn3 = 0.f;
    if (kq < 4) {
        const float* x0p = g_xg + ((size_t)0 * B_N + (4 * cl + kq)) * G_N;
        xc0 = __ldg(&x0p[0 * 256 + jg]); xc1 = __ldg(&x0p[1 * 256 + jg]);
        xc2 = __ldg(&x0p[2 * 256 + jg]); xc3 = __ldg(&x0p[3 * 256 + jg]);
        const float* x1p = g_xg + ((size_t)1 * B_N + (4 * cl + kq)) * G_N;
        xn0 = __ldg(&x1p[0 * 256 + jg]); xn1 = __ldg(&x1p[1 * 256 + jg]);
        xn2 = __ldg(&x1p[2 * 256 + jg]); xn3 = __ldg(&x1p[3 * 256 + jg]);
    }
    __syncthreads();
    asm volatile("barrier.cluster.arrive.aligned;" ::: "memory");
    asm volatile("barrier.cluster.wait.aligned;" ::: "memory");

    const int lane = t & 31;
    const int obase = lane & 24;

    ull t_mv = 0, t_upd = 0, t_wait = 0, c_a = 0, c_b = 0, c_c = 0, c_d = 0;

    for (int s = 0; s < S_LEN; s++) {
        if (tm) c_a = clock64();
        const float4* hb = h_s[s & 1];
        ull aif0 = 0, aif1 = 0, aif2 = 0, aif3 = 0;
        ull ago0 = 0, ago1 = 0, ago2 = 0, ago3 = 0;
#pragma unroll
        for (int kk = 0; kk < 32; kk++) {
            float4 hv = hb[(kk << 3) | kq];
            ull b0 = pack2(hv.x, hv.x), b1 = pack2(hv.y, hv.y);
            ull b2 = pack2(hv.z, hv.z), b3 = pack2(hv.w, hv.w);
            fma2(aif0, wif[kk], b0); fma2(ago0, wgo[kk], b0);
            fma2(aif1, wif[kk], b1); fma2(ago1, wgo[kk], b1);
            fma2(aif2, wif[kk], b2); fma2(ago2, wgo[kk], b2);
            fma2(aif3, wif[kk], b3); fma2(ago3, wgo[kk], b3);
        }
#pragma unroll
        for (int off = 1; off < 8; off <<= 1) {
            aif0 = add2(aif0, __shfl_xor_sync(0xffffffffu, aif0, off));
            aif1 = add2(aif1, __shfl_xor_sync(0xffffffffu, aif1, off));
            aif2 = add2(aif2, __shfl_xor_sync(0xffffffffu, aif2, off));
            aif3 = add2(aif3, __shfl_xor_sync(0xffffffffu, aif3, off));
            ago0 = add2(ago0, __shfl_xor_sync(0xffffffffu, ago0, off));
            ago1 = add2(ago1, __shfl_xor_sync(0xffffffffu, ago1, off));
            ago2 = add2(ago2, __shfl_xor_sync(0xffffffffu, ago2, off));
            ago3 = add2(ago3, __shfl_xor_sync(0xffffffffu, ago3, off));
        }
        if (tm) c_b = clock64();

        float hval = 0.0f;
        if (kq < 4) {
            ull aif = (kq == 0) ? aif0 : (kq == 1) ? aif1 : (kq == 2) ? aif2 : aif3;
            ull ago = (kq == 0) ? ago0 : (kq == 1) ? ago1 : (kq == 2) ? ago2 : ago3;
            float si, sf, sg, so;
            unpack2(aif, si, sf);
            unpack2(ago, sg, so);
            float iv = sigf(si + xc0);
            float fv = sigf(sf + xc1);
            float gv = tanhf_fast(sg + xc2);
            float ov = sigf(so + xc3);
            c = fv * c + iv * gv;
            hval = ov * tanhf_fast(c);
        }

        float hx = __shfl_sync(0xffffffffu, hval, obase + 0);
        float hy = __shfl_sync(0xffffffffu, hval, obase + 1);
        float hz = __shfl_sync(0xffffffffu, hval, obase + 2);
        float hw = __shfl_sync(0xffffffffu, hval, obase + 3);
        if (kq == 0) {
            float4 o4 = make_float4(hx, hy, hz, hw);
            int slot = (((s + 1) & 1) << 8) + jg;
#pragma unroll
            for (int p = 0; p < 8; p++) peer[p][slot] = o4;
            *(float4*)&g_hs[(((size_t)s * 16 + cl) * 256 + jg) * 4] = o4;
        }

        asm volatile("barrier.cluster.arrive.aligned;" ::: "memory");

        // rotate prefetch: cur <- nxt, issue LDG for s+2
        xc0 = xn0; xc1 = xn1; xc2 = xn2; xc3 = xn3;
        if (kq < 4 && s + 2 < S_LEN) {
            const float* xp = g_xg + ((size_t)(s + 2) * B_N + (4 * cl + kq)) * G_N;
            xn0 = __ldg(&xp[0 * 256 + jg]); xn1 = __ldg(&xp[1 * 256 + jg]);
            xn2 = __ldg(&xp[2 * 256 + jg]); xn3 = __ldg(&xp[3 * 256 + jg]);
        }
        if (tm) c_c = clock64();

        asm volatile("barrier.cluster.wait.aligned;" ::: "memory");
        if (tm) {
            c_d = clock64();
            t_mv   += c_b - c_a;
            t_upd  += c_c - c_b;
            t_wait += c_d - c_c;
        }
    }

    if (tm) printf("LSTM mv=%llu upd=%llu wait=%llu\n", t_mv, t_upd, t_wait);

    asm volatile("barrier.cluster.arrive.aligned;" ::: "memory");
    asm volatile("barrier.cluster.wait.aligned;" ::: "memory");
}

// =============== Phase 3: readout, g_hs is [s][cl][j][b4] ===============
__global__ void __launch_bounds__(256) readout_kernel(const float* __restrict__ Wout,
                                                      const float* __restrict__ bout,
                                                      float* __restrict__ y) {
    __shared__ float part[4][64];
    const int s = blockIdx.x;
    const int t = threadIdx.x;
    if (s == 0 && t == 0) printf("KR %llu\n", gtimer());
    const int p = t & 63;
    const int q = t >> 6;
    const float* hp = g_hs + (((size_t)s * 16 + (p >> 2)) * 256) * 4 + (p & 3);
    float acc = 0.0f;
#pragma unroll 8
    for (int j = q * 64; j < q * 64 + 64; j++)
        acc = fmaf(hp[(size_t)j * 4], Wout[j], acc);
    part[q][p] = acc;
    __syncthreads();
    if (t < 64) {
        float v = part[0][t] + part[1][t] + part[2][t] + part[3][t] + bout[0];
        y[s * 64 + t] = sigf(v);
    }
}

// =============== host launcher ===============
extern "C" void kernel_launch(void* const* d_in, const int* in_sizes, int n_in,
                              void* d_out, int out_size) {
    const float* pw   = (const float*)d_in[0];
    const float* Wemb = (const float*)d_in[1];
    const float* bemb = (const float*)d_in[2];
    const float* Wih  = (const float*)d_in[3];
    const float* Whh  = (const float*)d_in[4];
    const float* bih  = (const float*)d_in[5];
    const float* bhh  = (const float*)d_in[6];
    const float* Wout = (const float*)d_in[7];
    const float* bout = (const float*)d_in[8];
    const float* h0   = (const float*)d_in[9];
    const float* c0   = (const float*)d_in[10];
    float* y = (float*)d_out;

    static bool attrs_set = false;
    const int xg_smem = (2 * 128 * XP + 64 * TPCH) * (int)sizeof(float);
    if (!attrs_set) {
        cudaFuncSetAttribute(xgates_kernel, cudaFuncAttributeMaxDynamicSharedMemorySize, xg_smem);
        attrs_set = true;
    }

    emb_kernel<<<S_LEN, 256>>>(pw, Wemb, bemb);
    xgates_kernel<<<dim3(16, S_LEN), 128, xg_smem>>>(Wih, bih, bhh);
    lstm_kernel<<<128, 256>>>(Whh, h0, c0);
    readout_kernel<<<S_LEN, 256>>>(Wout, bout, y);
}